// round 12
// baseline (speedup 1.0000x reference)
#include <cuda_runtime.h>
#include <cuda_fp16.h>
#include <cstdint>

#define EDIM 256

__device__ __half g_prefh[2048 * EDIM];
__device__ __half g_bh[100000 * EDIM];
__device__ int    g_mask_mode;

static __device__ __forceinline__ uint32_t smem_u32(const void* p){
    uint32_t a;
    asm("{ .reg .u64 t; cvta.to.shared.u64 t, %1; cvt.u32.u64 %0, t; }" : "=r"(a) : "l"(p));
    return a;
}
static __device__ __forceinline__ void cp_async16(uint32_t dst, const void* src, int src_bytes){
    asm volatile("cp.async.ca.shared.global [%0], [%1], 16, %2;"
                 :: "r"(dst), "l"(src), "r"(src_bytes) : "memory");
}
#define CP_COMMIT() asm volatile("cp.async.commit_group;" ::: "memory")
#define CP_WAIT(n)  asm volatile("cp.async.wait_group %0;" :: "n"(n) : "memory")

static __device__ __forceinline__ void mma_f16(float* d, const uint32_t* a,
                                               uint32_t b0, uint32_t b1){
    asm volatile(
        "mma.sync.aligned.m16n8k16.row.col.f32.f16.f16.f32 "
        "{%0,%1,%2,%3}, {%4,%5,%6,%7}, {%8,%9}, {%0,%1,%2,%3};"
        : "+f"(d[0]), "+f"(d[1]), "+f"(d[2]), "+f"(d[3])
        : "r"(a[0]), "r"(a[1]), "r"(a[2]), "r"(a[3]), "r"(b0), "r"(b1));
}
static __device__ __forceinline__ void ldsm_x4(uint32_t* r, uint32_t addr){
    asm volatile("ldmatrix.sync.aligned.m8n8.x4.shared.b16 {%0,%1,%2,%3}, [%4];"
                 : "=r"(r[0]), "=r"(r[1]), "=r"(r[2]), "=r"(r[3]) : "r"(addr));
}

// ---------------- kernel 0: detect path_mask dtype ----------------
__global__ void detect_mask_kernel(const unsigned int* __restrict__ m){
    __shared__ int sf, sg;
    if (threadIdx.x == 0){ sf = 0; sg = 0; }
    __syncthreads();
    int lf = 0, lg = 0;
    for (int i = threadIdx.x; i < 3072; i += blockDim.x){
        unsigned v = m[i];
        if (v == 0x3F800000u) lf = 1;
        else if (v > 1u) lg = 1;
    }
    if (lf) atomicOr(&sf, 1);
    if (lg) atomicOr(&sg, 1);
    __syncthreads();
    if (threadIdx.x == 0) g_mask_mode = sf ? 2 : (sg ? 1 : 0);
}

// ---------------- kernel 1: fused attention + B-convert ----------------
__global__ void __launch_bounds__(128)
attn_conv_kernel(const int* __restrict__ user, const int* __restrict__ last_poi,
                 const int* __restrict__ path_nodes, const void* __restrict__ mask,
                 const int* __restrict__ nn_ptr,
                 const float* __restrict__ poi_emb, const float* __restrict__ tree_emb,
                 const float* __restrict__ w1, const float* __restrict__ b1,
                 const float* __restrict__ w2, const float* __restrict__ b2,
                 int Battn, int NB)
{
    if (blockIdx.x >= (unsigned)Battn){
        int i = ((blockIdx.x - Battn) * 128 + threadIdx.x) * 8;
        if (i + 8 <= NB){
            float4 v0 = *reinterpret_cast<const float4*>(poi_emb + i);
            float4 v1 = *reinterpret_cast<const float4*>(poi_emb + i + 4);
            __half2 h0 = __floats2half2_rn(v0.x, v0.y);
            __half2 h1 = __floats2half2_rn(v0.z, v0.w);
            __half2 h2 = __floats2half2_rn(v1.x, v1.y);
            __half2 h3 = __floats2half2_rn(v1.z, v1.w);
            uint4 o;
            o.x = *reinterpret_cast<uint32_t*>(&h0);
            o.y = *reinterpret_cast<uint32_t*>(&h1);
            o.z = *reinterpret_cast<uint32_t*>(&h2);
            o.w = *reinterpret_cast<uint32_t*>(&h3);
            *reinterpret_cast<uint4*>(&g_bh[i]) = o;
        } else {
            for (int j = i; j < NB; j++) g_bh[j] = __float2half_rn(poi_emb[j]);
        }
        return;
    }
    const int b = blockIdx.x, t = threadIdx.x;
    const int wid = t >> 5, lane = t & 31;
    __shared__ float lp[EDIM];
    __shared__ float pp[6][EDIM];
    __shared__ float hh[6][EDIM];
    __shared__ float red[6][4];

    const int mode = g_mask_mode;
    const int nn = nn_ptr ? nn_ptr[0] : 63;
    const int u = user[b];
    const int poi = last_poi[b];

    int nodes[6]; bool msk[6];
    #pragma unroll
    for (int l = 0; l < 6; l++) nodes[l] = path_nodes[b*6 + l];
    if (mode == 2){
        const float* mm = (const float*)mask;
        #pragma unroll
        for (int l = 0; l < 6; l++) msk[l] = (mm[b*6+l] != 0.f);
    } else if (mode == 1){
        const unsigned char* mm = (const unsigned char*)mask;
        #pragma unroll
        for (int l = 0; l < 6; l++) msk[l] = (mm[b*6+l] != 0);
    } else {
        const int* mm = (const int*)mask;
        #pragma unroll
        for (int l = 0; l < 6; l++) msk[l] = (mm[b*6+l] != 0);
    }

    for (int e = t; e < EDIM; e += 128) lp[e] = poi_emb[(size_t)poi*EDIM + e];
    for (int i = t; i < 6*EDIM; i += 128){
        int l = i >> 8, e = i & 255;
        pp[l][e] = tree_emb[((size_t)u*nn + nodes[l])*EDIM + e];
    }
    __syncthreads();
    for (int i = t; i < 6*EDIM; i += 128){
        int l = i >> 8, e = i & 255;
        hh[l][e] = tanhf(lp[e] + pp[l][e]);
    }
    __syncthreads();

    float acc[6] = {0.f,0.f,0.f,0.f,0.f,0.f};
    for (int e = 0; e < EDIM; e++){
        float w = w1[e*128 + t];
        #pragma unroll
        for (int l = 0; l < 6; l++) acc[l] += hh[l][e] * w;
    }
    const float b1j = b1[t], w2j = w2[t];
    float part[6];
    #pragma unroll
    for (int l = 0; l < 6; l++) part[l] = fmaxf(acc[l] + b1j, 0.f) * w2j;
    #pragma unroll
    for (int o = 16; o > 0; o >>= 1){
        #pragma unroll
        for (int l = 0; l < 6; l++) part[l] += __shfl_xor_sync(0xFFFFFFFFu, part[l], o);
    }
    if (lane == 0){
        #pragma unroll
        for (int l = 0; l < 6; l++) red[l][wid] = part[l];
    }
    __syncthreads();

    const float b2v = b2[0];
    float a[6], amax = -3.0e38f;
    #pragma unroll
    for (int l = 0; l < 6; l++){
        float v = red[l][0] + red[l][1] + red[l][2] + red[l][3] + b2v;
        if (!msk[l]) v = -1e9f;
        a[l] = v; amax = fmaxf(amax, v);
    }
    float s = 0.f, aw[6];
    #pragma unroll
    for (int l = 0; l < 6; l++){ aw[l] = expf(a[l] - amax); s += aw[l]; }
    const float inv = 1.f / s;
    for (int e = t; e < EDIM; e += 128){
        float o = 0.f;
        #pragma unroll
        for (int l = 0; l < 6; l++) o += aw[l] * pp[l][e];
        g_prefh[(size_t)b*EDIM + e] = __float2half_rn(o * inv);
    }
}

// ---------------- kernel 2: GEMM, A-resident, K=64 chunks, reg-pipelined ----------------
#define AROWH 264                      // 256 data + 8 pad halves; 528 B row
#define A_BYTES (256*AROWH*2)          // 135168
#define BROWH 72                       // 64 data + 8 pad halves; 144 B row
#define BSTAGE_BYTES (128*BROWH*2)     // 18432
#define NSTAGE 3
#define B_OFF A_BYTES
#define GSMEM_BYTES (A_BYTES + NSTAGE*BSTAGE_BYTES)   // 190464

__global__ void __launch_bounds__(256, 1)
gemm_kernel(float* __restrict__ out, int Brows, int Ncols, int tiles, int nsplit)
{
    extern __shared__ char smem[];
    const uint32_t sb = smem_u32(smem);
    const int t = threadIdx.x;
    const int wid = t >> 5, lane = t & 31;
    const int g = lane >> 2, tq = lane & 3;
    const int wm = wid >> 1, wn = wid & 1;      // 4 x 2 warp grid, 64x64 tiles
    const int m_base = blockIdx.x * 256;
    const int strip = blockIdx.y;

    const int ti0 = (int)((long long)strip * tiles / nsplit);
    const int ti1 = (int)((long long)(strip + 1) * tiles / nsplit);
    const int Q = (ti1 - ti0) * 4;              // K=64 chunks
    if (Q <= 0) return;

    // ---- resident A tile (256 x 256 halves), its own cp.async group ----
    #pragma unroll
    for (int it = 0; it < 32; it++){
        int idx = t + it*256;
        int row = idx >> 5, seg = idx & 31;
        int gm = m_base + row;
        const __half* src = &g_prefh[(size_t)(gm < Brows ? gm : 0)*EDIM + seg*8];
        cp_async16(sb + row*(AROWH*2) + seg*16, src, gm < Brows ? 16 : 0);
    }
    CP_COMMIT();

    // ldmatrix lane->pointer precompute
    const int lr  = lane & 7;
    const int sel = lane >> 3;
    uint32_t a_off[4];
    #pragma unroll
    for (int i = 0; i < 4; i++){
        int row = wm*64 + i*16 + (sel & 1)*8 + lr;
        a_off[i] = (uint32_t)(row*(AROWH*2) + ((sel >> 1)*8)*2);
    }
    uint32_t b_off[4];
    #pragma unroll
    for (int jp = 0; jp < 4; jp++){
        int n = wn*64 + jp*16 + (sel >> 1)*8 + lr;
        b_off[jp] = (uint32_t)(n*(BROWH*2) + ((sel & 1)*8)*2);
    }

    const int brow = t >> 1;          // 0..127
    const int bs0 = (t & 1) * 4;      // 4x16B per thread

    float acc[4][8][4];
    #pragma unroll
    for (int i = 0; i < 4; i++)
        #pragma unroll
        for (int j = 0; j < 8; j++)
            #pragma unroll
            for (int r = 0; r < 4; r++) acc[i][j][r] = 0.f;

    auto prefetchB = [&](int q){
        if (q < Q){
            const int tile = ti0 + (q >> 2);
            const int kc = q & 3;
            const int n_base = tile * 128;
            const uint32_t base = sb + B_OFF + (q % NSTAGE)*BSTAGE_BYTES;
            const int gn = n_base + brow;
            const __half* srcr = &g_bh[(size_t)(gn < Ncols ? gn : 0)*EDIM + kc*64];
            const int nb = (gn < Ncols) ? 16 : 0;
            #pragma unroll
            for (int s = 0; s < 4; s++){
                int seg = bs0 + s;
                cp_async16(base + brow*(BROWH*2) + seg*16, srcr + seg*8, nb);
            }
        }
        CP_COMMIT();
    };

    uint32_t afr[2][4][4];
    uint32_t bfr[2][8][2];

    auto load_frags = [&](int q, int ks, int buf){
        const uint32_t stage = sb + B_OFF + (q % NSTAGE)*BSTAGE_BYTES;
        const uint32_t ka = (uint32_t)((q & 3)*128 + ks*32);   // A k byte offset
        const uint32_t kb = (uint32_t)(ks*32);                 // B k byte offset
        #pragma unroll
        for (int i = 0; i < 4; i++)
            ldsm_x4(afr[buf][i], sb + a_off[i] + ka);
        #pragma unroll
        for (int jp = 0; jp < 4; jp++){
            uint32_t r[4];
            ldsm_x4(r, stage + b_off[jp] + kb);
            bfr[buf][2*jp][0]   = r[0];  bfr[buf][2*jp][1]   = r[1];
            bfr[buf][2*jp+1][0] = r[2];  bfr[buf][2*jp+1][1] = r[3];
        }
    };

    auto mma_all = [&](int buf){
        #pragma unroll
        for (int i = 0; i < 4; i++)
            #pragma unroll
            for (int j = 0; j < 8; j++)
                mma_f16(acc[i][j], afr[buf][i], bfr[buf][j][0], bfr[buf][j][1]);
    };

    // prologue groups: {A, B0, B1}
    prefetchB(0); prefetchB(1);

    for (int q = 0; q < Q; q++){
        CP_WAIT(1);                   // chunk q (and A) resident
        __syncthreads();
        prefetchB(q + 2);             // overwrites slot (q-1)%3: consumed last iter

        load_frags(q, 0, 0);
        load_frags(q, 1, 1);  mma_all(0);
        load_frags(q, 2, 0);  mma_all(1);
        load_frags(q, 3, 1);  mma_all(0);
        mma_all(1);

        if ((q & 3) == 3){
            const int n_base = (ti0 + (q >> 2)) * 128;
            #pragma unroll
            for (int i = 0; i < 4; i++){
                const int row0 = m_base + wm*64 + i*16 + g;
                #pragma unroll
                for (int j = 0; j < 8; j++){
                    const int col = n_base + wn*64 + j*8 + 2*tq;
                    if (col < Ncols && row0 < Brows){
                        float2 v0 = make_float2(acc[i][j][0], acc[i][j][1]);
                        float2 v1 = make_float2(acc[i][j][2], acc[i][j][3]);
                        __stcs(reinterpret_cast<float2*>(&out[(size_t)row0*Ncols + col]), v0);
                        __stcs(reinterpret_cast<float2*>(&out[(size_t)(row0+8)*Ncols + col]), v1);
                    }
                    #pragma unroll
                    for (int r = 0; r < 4; r++) acc[i][j][r] = 0.f;
                }
            }
        }
    }
}

// ---------------- launch ----------------
extern "C" void kernel_launch(void* const* d_in, const int* in_sizes, int n_in,
                              void* d_out, int out_size)
{
    const int* user       = (const int*)d_in[0];
    const int* last_poi   = (const int*)d_in[1];
    const int* path_nodes = (const int*)d_in[2];
    const void* mask      = d_in[3];
    const int* nn_ptr = nullptr;
    int k = 4;
    if (n_in >= 11){ nn_ptr = (const int*)d_in[4]; k = 5; }
    const float* poi_emb  = (const float*)d_in[k+0];
    const float* tree_emb = (const float*)d_in[k+1];
    const float* w1 = (const float*)d_in[k+2];
    const float* b1 = (const float*)d_in[k+3];
    const float* w2 = (const float*)d_in[k+4];
    const float* b2 = (const float*)d_in[k+5];
    float* out = (float*)d_out;

    const int B  = in_sizes[0];
    const int NB = in_sizes[k+0];
    const int NP = NB / EDIM;
    const int tiles = (NP + 127) / 128;
    const int gridM = (B + 255) / 256;
    int nsplit = 148 / gridM; if (nsplit < 1) nsplit = 1;   // exactly one wave
    if (nsplit > tiles) nsplit = tiles;
    const int convBlocks = (NB + 1023) / 1024;

    detect_mask_kernel<<<1, 256>>>((const unsigned int*)mask);
    attn_conv_kernel<<<B + convBlocks, 128>>>(user, last_poi, path_nodes, mask, nn_ptr,
                                              poi_emb, tree_emb, w1, b1, w2, b2, B, NB);
    cudaFuncSetAttribute(gemm_kernel,
                         cudaFuncAttributeMaxDynamicSharedMemorySize, GSMEM_BYTES);
    dim3 grid(gridM, nsplit);
    gemm_kernel<<<grid, 256, GSMEM_BYTES>>>(out, B, NP, tiles, nsplit);
}

// round 13
// speedup vs baseline: 1.2444x; 1.2444x over previous
#include <cuda_runtime.h>
#include <cuda_fp16.h>
#include <cstdint>

#define EDIM 256

__device__ __half g_prefh[2048 * EDIM];
__device__ __half g_bh[100000 * EDIM];
__device__ int    g_mask_mode;

static __device__ __forceinline__ uint32_t smem_u32(const void* p){
    uint32_t a;
    asm("{ .reg .u64 t; cvta.to.shared.u64 t, %1; cvt.u32.u64 %0, t; }" : "=r"(a) : "l"(p));
    return a;
}
static __device__ __forceinline__ void cp_async16(uint32_t dst, const void* src, int src_bytes){
    asm volatile("cp.async.ca.shared.global [%0], [%1], 16, %2;"
                 :: "r"(dst), "l"(src), "r"(src_bytes) : "memory");
}
#define CP_COMMIT() asm volatile("cp.async.commit_group;" ::: "memory")
#define CP_WAIT(n)  asm volatile("cp.async.wait_group %0;" :: "n"(n) : "memory")

static __device__ __forceinline__ void mma_f16(float* d, const uint32_t* a,
                                               uint32_t b0, uint32_t b1){
    asm volatile(
        "mma.sync.aligned.m16n8k16.row.col.f32.f16.f16.f32 "
        "{%0,%1,%2,%3}, {%4,%5,%6,%7}, {%8,%9}, {%0,%1,%2,%3};"
        : "+f"(d[0]), "+f"(d[1]), "+f"(d[2]), "+f"(d[3])
        : "r"(a[0]), "r"(a[1]), "r"(a[2]), "r"(a[3]), "r"(b0), "r"(b1));
}
static __device__ __forceinline__ void ldsm_x4(uint32_t* r, uint32_t addr){
    asm volatile("ldmatrix.sync.aligned.m8n8.x4.shared.b16 {%0,%1,%2,%3}, [%4];"
                 : "=r"(r[0]), "=r"(r[1]), "=r"(r[2]), "=r"(r[3]) : "r"(addr));
}

// ---------------- kernel 0: detect path_mask dtype ----------------
__global__ void detect_mask_kernel(const unsigned int* __restrict__ m){
    __shared__ int sf, sg;
    if (threadIdx.x == 0){ sf = 0; sg = 0; }
    __syncthreads();
    int lf = 0, lg = 0;
    for (int i = threadIdx.x; i < 3072; i += blockDim.x){
        unsigned v = m[i];
        if (v == 0x3F800000u) lf = 1;
        else if (v > 1u) lg = 1;
    }
    if (lf) atomicOr(&sf, 1);
    if (lg) atomicOr(&sg, 1);
    __syncthreads();
    if (threadIdx.x == 0) g_mask_mode = sf ? 2 : (sg ? 1 : 0);
}

// ---------------- kernel 1: fused attention + B-convert ----------------
__global__ void __launch_bounds__(128)
attn_conv_kernel(const int* __restrict__ user, const int* __restrict__ last_poi,
                 const int* __restrict__ path_nodes, const void* __restrict__ mask,
                 const int* __restrict__ nn_ptr,
                 const float* __restrict__ poi_emb, const float* __restrict__ tree_emb,
                 const float* __restrict__ w1, const float* __restrict__ b1,
                 const float* __restrict__ w2, const float* __restrict__ b2,
                 int Battn, int NB)
{
    if (blockIdx.x >= (unsigned)Battn){
        int i = ((blockIdx.x - Battn) * 128 + threadIdx.x) * 8;
        if (i + 8 <= NB){
            float4 v0 = *reinterpret_cast<const float4*>(poi_emb + i);
            float4 v1 = *reinterpret_cast<const float4*>(poi_emb + i + 4);
            __half2 h0 = __floats2half2_rn(v0.x, v0.y);
            __half2 h1 = __floats2half2_rn(v0.z, v0.w);
            __half2 h2 = __floats2half2_rn(v1.x, v1.y);
            __half2 h3 = __floats2half2_rn(v1.z, v1.w);
            uint4 o;
            o.x = *reinterpret_cast<uint32_t*>(&h0);
            o.y = *reinterpret_cast<uint32_t*>(&h1);
            o.z = *reinterpret_cast<uint32_t*>(&h2);
            o.w = *reinterpret_cast<uint32_t*>(&h3);
            *reinterpret_cast<uint4*>(&g_bh[i]) = o;
        } else {
            for (int j = i; j < NB; j++) g_bh[j] = __float2half_rn(poi_emb[j]);
        }
        return;
    }
    const int b = blockIdx.x, t = threadIdx.x;
    const int wid = t >> 5, lane = t & 31;
    __shared__ float lp[EDIM];
    __shared__ float pp[6][EDIM];
    __shared__ float hh[6][EDIM];
    __shared__ float red[6][4];

    const int mode = g_mask_mode;
    const int nn = nn_ptr ? nn_ptr[0] : 63;
    const int u = user[b];
    const int poi = last_poi[b];

    int nodes[6]; bool msk[6];
    #pragma unroll
    for (int l = 0; l < 6; l++) nodes[l] = path_nodes[b*6 + l];
    if (mode == 2){
        const float* mm = (const float*)mask;
        #pragma unroll
        for (int l = 0; l < 6; l++) msk[l] = (mm[b*6+l] != 0.f);
    } else if (mode == 1){
        const unsigned char* mm = (const unsigned char*)mask;
        #pragma unroll
        for (int l = 0; l < 6; l++) msk[l] = (mm[b*6+l] != 0);
    } else {
        const int* mm = (const int*)mask;
        #pragma unroll
        for (int l = 0; l < 6; l++) msk[l] = (mm[b*6+l] != 0);
    }

    for (int e = t; e < EDIM; e += 128) lp[e] = poi_emb[(size_t)poi*EDIM + e];
    for (int i = t; i < 6*EDIM; i += 128){
        int l = i >> 8, e = i & 255;
        pp[l][e] = tree_emb[((size_t)u*nn + nodes[l])*EDIM + e];
    }
    __syncthreads();
    for (int i = t; i < 6*EDIM; i += 128){
        int l = i >> 8, e = i & 255;
        hh[l][e] = tanhf(lp[e] + pp[l][e]);
    }
    __syncthreads();

    float acc[6] = {0.f,0.f,0.f,0.f,0.f,0.f};
    for (int e = 0; e < EDIM; e++){
        float w = w1[e*128 + t];
        #pragma unroll
        for (int l = 0; l < 6; l++) acc[l] += hh[l][e] * w;
    }
    const float b1j = b1[t], w2j = w2[t];
    float part[6];
    #pragma unroll
    for (int l = 0; l < 6; l++) part[l] = fmaxf(acc[l] + b1j, 0.f) * w2j;
    #pragma unroll
    for (int o = 16; o > 0; o >>= 1){
        #pragma unroll
        for (int l = 0; l < 6; l++) part[l] += __shfl_xor_sync(0xFFFFFFFFu, part[l], o);
    }
    if (lane == 0){
        #pragma unroll
        for (int l = 0; l < 6; l++) red[l][wid] = part[l];
    }
    __syncthreads();

    const float b2v = b2[0];
    float a[6], amax = -3.0e38f;
    #pragma unroll
    for (int l = 0; l < 6; l++){
        float v = red[l][0] + red[l][1] + red[l][2] + red[l][3] + b2v;
        if (!msk[l]) v = -1e9f;
        a[l] = v; amax = fmaxf(amax, v);
    }
    float s = 0.f, aw[6];
    #pragma unroll
    for (int l = 0; l < 6; l++){ aw[l] = expf(a[l] - amax); s += aw[l]; }
    const float inv = 1.f / s;
    for (int e = t; e < EDIM; e += 128){
        float o = 0.f;
        #pragma unroll
        for (int l = 0; l < 6; l++) o += aw[l] * pp[l][e];
        g_prefh[(size_t)b*EDIM + e] = __float2half_rn(o * inv);
    }
}

// ---------------- kernel 2: GEMM, A-resident + reg-pipelined + staged epilogue ----------------
#define AROWH 264                      // 256 data + 8 pad halves; 528 B row
#define A_BYTES (256*AROWH*2)          // 135168
#define ROWH 40
#define BSTAGE_BYTES (128*ROWH*2)      // 10240
#define NSTAGE 4
#define B_OFF A_BYTES
#define EP_OFF (A_BYTES + NSTAGE*BSTAGE_BYTES)        // 176128
#define EPW_WORDS (16*72)                              // per-warp 16 rows x 72 f32
#define GSMEM_BYTES (EP_OFF + 8*EPW_WORDS*4)           // 176128+36864 = 212992

__global__ void __launch_bounds__(256, 1)
gemm_kernel(float* __restrict__ out, int Brows, int Ncols, int tiles, int nsplit)
{
    extern __shared__ char smem[];
    const uint32_t sb = smem_u32(smem);
    const int t = threadIdx.x;
    const int wid = t >> 5, lane = t & 31;
    const int g = lane >> 2, tq = lane & 3;
    const int wm = wid >> 1, wn = wid & 1;      // 4 x 2 warp grid, 64x64 tiles
    const int m_base = blockIdx.x * 256;
    const int strip = blockIdx.y;

    const int ti0 = (int)((long long)strip * tiles / nsplit);
    const int ti1 = (int)((long long)(strip + 1) * tiles / nsplit);
    const int Q = (ti1 - ti0) * 8;
    if (Q <= 0) return;

    // ---- resident A tile (256 x 256 halves), its own cp.async group ----
    #pragma unroll
    for (int it = 0; it < 32; it++){
        int idx = t + it*256;
        int row = idx >> 5, seg = idx & 31;
        int gm = m_base + row;
        const __half* src = &g_prefh[(size_t)(gm < Brows ? gm : 0)*EDIM + seg*8];
        cp_async16(sb + row*(AROWH*2) + seg*16, src, gm < Brows ? 16 : 0);
    }
    CP_COMMIT();

    // ldmatrix lane->pointer precompute
    const int lr  = lane & 7;
    const int sel = lane >> 3;
    uint32_t a_off[4];
    #pragma unroll
    for (int i = 0; i < 4; i++){
        int row = wm*64 + i*16 + (sel & 1)*8 + lr;
        a_off[i] = (uint32_t)(row*(AROWH*2) + ((sel >> 1)*8)*2);
    }
    uint32_t b_off[4];
    #pragma unroll
    for (int jp = 0; jp < 4; jp++){
        int n = wn*64 + jp*16 + (sel >> 1)*8 + lr;
        b_off[jp] = (uint32_t)(n*(ROWH*2) + ((sel & 1)*8)*2);
    }

    const int lrow = t >> 1;
    const int lseg2 = t & 1;

    float acc[4][8][4];
    #pragma unroll
    for (int i = 0; i < 4; i++)
        #pragma unroll
        for (int j = 0; j < 8; j++)
            #pragma unroll
            for (int r = 0; r < 4; r++) acc[i][j][r] = 0.f;

    auto prefetchB = [&](int q){
        if (q < Q){
            const int tile = ti0 + (q >> 3);
            const int kc = q & 7;
            const int n_base = tile * 128;
            const uint32_t base = sb + B_OFF + (q % NSTAGE)*BSTAGE_BYTES;
            #pragma unroll
            for (int s2 = 0; s2 < 2; s2++){
                int seg = lseg2*2 + s2;
                int gn = n_base + lrow;
                const __half* src = &g_bh[(size_t)(gn < Ncols ? gn : 0)*EDIM + kc*32 + seg*8];
                cp_async16(base + lrow*(ROWH*2) + seg*16, src, gn < Ncols ? 16 : 0);
            }
        }
        CP_COMMIT();
    };

    uint32_t afr[2][4][4];
    uint32_t bfr[2][8][2];

    auto load_frags = [&](int q, int ks, int buf){
        const uint32_t stage = sb + B_OFF + (q % NSTAGE)*BSTAGE_BYTES;
        const uint32_t ka = (uint32_t)((q & 7)*64 + ks*32);
        const uint32_t kb = (uint32_t)(ks*32);
        #pragma unroll
        for (int i = 0; i < 4; i++)
            ldsm_x4(afr[buf][i], sb + a_off[i] + ka);
        #pragma unroll
        for (int jp = 0; jp < 4; jp++){
            uint32_t r[4];
            ldsm_x4(r, stage + b_off[jp] + kb);
            bfr[buf][2*jp][0]   = r[0];  bfr[buf][2*jp][1]   = r[1];
            bfr[buf][2*jp+1][0] = r[2];  bfr[buf][2*jp+1][1] = r[3];
        }
    };

    auto mma_all = [&](int buf){
        #pragma unroll
        for (int i = 0; i < 4; i++)
            #pragma unroll
            for (int j = 0; j < 8; j++)
                mma_f16(acc[i][j], afr[buf][i], bfr[buf][j][0], bfr[buf][j][1]);
    };

    float* stg = reinterpret_cast<float*>(smem + EP_OFF) + wid * EPW_WORDS;

    // prologue: groups = {A, B0, B1, B2}
    prefetchB(0); prefetchB(1); prefetchB(2);
    CP_WAIT(2);
    __syncthreads();
    load_frags(0, 0, 0);

    for (int q = 0; q < Q; q++){
        load_frags(q, 1, 1);
        mma_all(0);

        CP_WAIT(1);
        __syncthreads();
        prefetchB(q + 3);

        if (q + 1 < Q) load_frags(q + 1, 0, 0);
        mma_all(1);

        if ((q & 7) == 7){
            // per-warp smem-staged coalesced epilogue
            const int n_base = (ti0 + (q >> 3)) * 128;
            const int col_b = n_base + wn*64;
            #pragma unroll
            for (int i = 0; i < 4; i++){
                #pragma unroll
                for (int j = 0; j < 8; j++){
                    const int c = j*8 + 2*tq;
                    stg[g*72 + c]       = acc[i][j][0];
                    stg[g*72 + c + 1]   = acc[i][j][1];
                    stg[(g+8)*72 + c]     = acc[i][j][2];
                    stg[(g+8)*72 + c + 1] = acc[i][j][3];
                    #pragma unroll
                    for (int r = 0; r < 4; r++) acc[i][j][r] = 0.f;
                }
                __syncwarp();
                const int row_b = m_base + wm*64 + i*16;
                #pragma unroll
                for (int p = 0; p < 8; p++){
                    int f = lane + p*32;
                    int r = f >> 4, c4 = f & 15;
                    float4 v = *reinterpret_cast<float4*>(&stg[r*72 + c4*4]);
                    int row = row_b + r;
                    int col = col_b + c4*4;
                    if (col < Ncols && row < Brows)
                        __stcs(reinterpret_cast<float4*>(&out[(size_t)row*Ncols + col]), v);
                }
                __syncwarp();
            }
        }
    }
}

// ---------------- launch ----------------
extern "C" void kernel_launch(void* const* d_in, const int* in_sizes, int n_in,
                              void* d_out, int out_size)
{
    const int* user       = (const int*)d_in[0];
    const int* last_poi   = (const int*)d_in[1];
    const int* path_nodes = (const int*)d_in[2];
    const void* mask      = d_in[3];
    const int* nn_ptr = nullptr;
    int k = 4;
    if (n_in >= 11){ nn_ptr = (const int*)d_in[4]; k = 5; }
    const float* poi_emb  = (const float*)d_in[k+0];
    const float* tree_emb = (const float*)d_in[k+1];
    const float* w1 = (const float*)d_in[k+2];
    const float* b1 = (const float*)d_in[k+3];
    const float* w2 = (const float*)d_in[k+4];
    const float* b2 = (const float*)d_in[k+5];
    float* out = (float*)d_out;

    const int B  = in_sizes[0];
    const int NB = in_sizes[k+0];
    const int NP = NB / EDIM;
    const int tiles = (NP + 127) / 128;
    const int gridM = (B + 255) / 256;
    int nsplit = 296 / gridM; if (nsplit < 1) nsplit = 1;
    if (nsplit > tiles) nsplit = tiles;
    const int convBlocks = (NB + 1023) / 1024;

    detect_mask_kernel<<<1, 256>>>((const unsigned int*)mask);
    attn_conv_kernel<<<B + convBlocks, 128>>>(user, last_poi, path_nodes, mask, nn_ptr,
                                              poi_emb, tree_emb, w1, b1, w2, b2, B, NB);
    cudaFuncSetAttribute(gemm_kernel,
                         cudaFuncAttributeMaxDynamicSharedMemorySize, GSMEM_BYTES);
    dim3 grid(gridM, nsplit);
    gemm_kernel<<<grid, 256, GSMEM_BYTES>>>(out, B, NP, tiles, nsplit);
}